// round 9
// baseline (speedup 1.0000x reference)
#include <cuda_runtime.h>
#include <cuda_fp16.h>
#include <cstdint>

namespace {

constexpr int THREADS = 128;             // 4 warps/CTA, 5 CTAs/SM -> 20 warps
constexpr int NWARP   = 4;
constexpr int MT      = 2;               // 16-row m-tiles per warp
constexpr int WARP_M  = 16 * MT;         // 32 rows / warp
constexpr int CTA_M   = NWARP * WARP_M;  // 128 rows / CTA
constexpr int LDD     = 24;              // density smem ld (halves), conflict-free

// Per-lane permuted weight tables: entry (nph, c, lane) = uint4 holding the
// (b0,b1) B-fragment pairs for k-tiles 2c, 2c+1 of n-group nph, as consumed by
// lane `lane`. 16B lane stride -> conflict-free LDS.128.
struct SmemLayout {
    uint4 p_d0[8 * 1 * 32];
    uint4 p_c0[8 * 1 * 32];
    uint4 p_d1[2 * 2 * 32];
    uint4 p_c1[8 * 2 * 32];
    uint4 p_c2[8 * 2 * 32];
    uint4 p_c3[1 * 2 * 32];
    __half den[NWARP][WARP_M * LDD];  // d1 outputs (16 half cols) for concat shift
};  // ~33 KB -> 5 CTAs/SM

__device__ __forceinline__ uint32_t h2u(float x, float y) {
    __half2 h = __floats2half2_rn(x, y);
    return *reinterpret_cast<uint32_t*>(&h);
}
__device__ __forceinline__ uint32_t hh2u(__half x, __half y) {
    __half2 h = __halves2half2(x, y);
    return *reinterpret_cast<uint32_t*>(&h);
}
__device__ __forceinline__ uint32_t relu2(uint32_t p) {
    __half2 h = *reinterpret_cast<__half2*>(&p);
    __half2 r = __hmax2(h, __half2(__float2half_rn(0.f), __float2half_rn(0.f)));
    return *reinterpret_cast<uint32_t*>(&r);
}

__device__ __forceinline__ void mma16816(float c[4], const uint32_t a[4],
                                         uint32_t b0, uint32_t b1) {
    asm volatile(
        "mma.sync.aligned.m16n8k16.row.col.f32.f16.f16.f32 "
        "{%0,%1,%2,%3},{%4,%5,%6,%7},{%8,%9},{%0,%1,%2,%3};\n"
        : "+f"(c[0]), "+f"(c[1]), "+f"(c[2]), "+f"(c[3])
        : "r"(a[0]), "r"(a[1]), "r"(a[2]), "r"(a[3]), "r"(b0), "r"(b1));
}

// Stage a [Nout x Kin] f32 row-major weight matrix into the permuted table.
__device__ void stage_perm(uint4* dst, const float* __restrict__ W, int Nout,
                           int Kin, int NPH, int CH, int tid) {
    const int total = NPH * CH * 32;
    for (int e = tid; e < total; e += THREADS) {
        int lane = e & 31;
        int c    = (e >> 5) % CH;
        int nph  = e / (32 * CH);
        int row  = (nph >> 1) * 16 + (nph & 1) * 8 + (lane >> 2);
        int col  = (lane & 3) * 2;
        int k0   = c * 32;
        auto rd = [&](int cc) -> float {
            return (row < Nout && cc < Kin) ? W[row * Kin + cc] : 0.0f;
        };
        uint4 v;
        v.x = h2u(rd(k0 + col),          rd(k0 + col + 1));
        v.y = h2u(rd(k0 + col + 8),      rd(k0 + col + 9));
        v.z = h2u(rd(k0 + 16 + col),     rd(k0 + 16 + col + 1));
        v.w = h2u(rd(k0 + 16 + col + 8), rd(k0 + 16 + col + 9));
        dst[e] = v;
    }
}

// Register-chained relu layer: one LDS.128 per (np,h,chunk) feeds 2*MT HMMAs.
template <int KT, int NP>
__device__ __forceinline__ void layer_chain(const uint32_t (&A)[MT][4][4],
                                            const uint4* __restrict__ pw,
                                            uint32_t (&O)[MT][4][4]) {
    constexpr int CH = KT / 2;
#pragma unroll
    for (int np = 0; np < NP; np++) {
        float acc[MT][2][4];
#pragma unroll
        for (int m = 0; m < MT; m++)
#pragma unroll
            for (int h = 0; h < 2; h++)
#pragma unroll
                for (int e = 0; e < 4; e++) acc[m][h][e] = 0.0f;
#pragma unroll
        for (int h = 0; h < 2; h++) {
#pragma unroll
            for (int c = 0; c < CH; c++) {
                uint4 v = pw[((np * 2 + h) * CH + c) * 32];
#pragma unroll
                for (int m = 0; m < MT; m++) {
                    mma16816(acc[m][h], A[m][2 * c],     v.x, v.y);
                    mma16816(acc[m][h], A[m][2 * c + 1], v.z, v.w);
                }
            }
        }
#pragma unroll
        for (int m = 0; m < MT; m++) {
            O[m][np][0] = relu2(h2u(acc[m][0][0], acc[m][0][1]));
            O[m][np][1] = relu2(h2u(acc[m][0][2], acc[m][0][3]));
            O[m][np][2] = relu2(h2u(acc[m][1][0], acc[m][1][1]));
            O[m][np][3] = relu2(h2u(acc[m][1][2], acc[m][1][3]));
        }
    }
}

// Load 32-wide hash rows for one warp-tile into Ab[m][0..1] (streaming).
__device__ __forceinline__ void load_hash(uint32_t (&Ab)[MT][4][4],
                                          const float* __restrict__ hash,
                                          size_t row0, int g, int i2) {
#pragma unroll
    for (int m = 0; m < MT; m++) {
        const float2* h0 =
            reinterpret_cast<const float2*>(hash + (row0 + m * 16 + g) * 32);
        const float2* h8 =
            reinterpret_cast<const float2*>(hash + (row0 + m * 16 + g + 8) * 32);
#pragma unroll
        for (int kt = 0; kt < 2; kt++) {
            float2 v0 = __ldcs(h0 + kt * 8 + (i2 >> 1));
            float2 v1 = __ldcs(h8 + kt * 8 + (i2 >> 1));
            float2 v2 = __ldcs(h0 + kt * 8 + 4 + (i2 >> 1));
            float2 v3 = __ldcs(h8 + kt * 8 + 4 + (i2 >> 1));
            Ab[m][kt][0] = h2u(v0.x, v0.y);
            Ab[m][kt][1] = h2u(v1.x, v1.y);
            Ab[m][kt][2] = h2u(v2.x, v2.y);
            Ab[m][kt][3] = h2u(v3.x, v3.y);
        }
    }
}

}  // namespace

__global__ void __launch_bounds__(THREADS, 5)
nerf_fused_kernel(const float* __restrict__ hash, const float* __restrict__ sh,
                  const float* __restrict__ d0, const float* __restrict__ d1,
                  const float* __restrict__ c0, const float* __restrict__ c1,
                  const float* __restrict__ c2, const float* __restrict__ c3,
                  float* __restrict__ out, int n_tiles) {
    __shared__ SmemLayout S;
    const int tid  = threadIdx.x;
    const int warp = tid >> 5;
    const int lane = tid & 31;
    const int g    = lane >> 2;       // row-in-tile-half
    const int i2   = (lane & 3) * 2;  // column pair base

    // ---- Stage permuted weights once per CTA ----
    stage_perm(S.p_d0, d0, 64, 32, 8, 1, tid);
    stage_perm(S.p_c0, c0, 64, 31, 8, 1, tid);
    stage_perm(S.p_d1, d1, 16, 64, 2, 2, tid);
    stage_perm(S.p_c1, c1, 64, 64, 8, 2, tid);
    stage_perm(S.p_c2, c2, 64, 64, 8, 2, tid);
    stage_perm(S.p_c3, c3,  3, 64, 1, 2, tid);
    __syncthreads();  // only block barrier

    __half* den = S.den[warp];
    const uint4* pw_d0 = S.p_d0 + lane;
    const uint4* pw_c0 = S.p_c0 + lane;
    const uint4* pw_d1 = S.p_d1 + lane;
    const uint4* pw_c1 = S.p_c1 + lane;
    const uint4* pw_c2 = S.p_c2 + lane;
    const uint4* pw_c3 = S.p_c3 + lane;
    float4* out4 = reinterpret_cast<float4*>(out);

    uint32_t Aa[MT][4][4];  // ping
    uint32_t Ab[MT][4][4];  // pong; Ab[m][0..1] holds hash input at loop top

    int tile = blockIdx.x;
    if (tile < n_tiles)
        load_hash(Ab, hash, (size_t)tile * CTA_M + warp * WARP_M, g, i2);

    for (; tile < n_tiles;) {
        const size_t row0 = (size_t)tile * CTA_M + warp * WARP_M;

        // ---- d0: relu(hash @ d0^T), hash already in Ab ----
        layer_chain<2, 4>(Ab, pw_d0, Aa);

        // ---- d1: h @ d1^T -> density (den, half) + sigma (regs) ----
        float sig[MT][2];
        {
            float dacc[MT][2][4];
#pragma unroll
            for (int m = 0; m < MT; m++)
#pragma unroll
                for (int h = 0; h < 2; h++)
#pragma unroll
                    for (int e = 0; e < 4; e++) dacc[m][h][e] = 0.0f;
#pragma unroll
            for (int h = 0; h < 2; h++) {
#pragma unroll
                for (int c = 0; c < 2; c++) {
                    uint4 v = pw_d1[(h * 2 + c) * 32];
#pragma unroll
                    for (int m = 0; m < MT; m++) {
                        mma16816(dacc[m][h], Aa[m][2 * c],     v.x, v.y);
                        mma16816(dacc[m][h], Aa[m][2 * c + 1], v.z, v.w);
                    }
                }
            }
#pragma unroll
            for (int m = 0; m < MT; m++) {
                // sigma = col 0: meaningful on i2==0 lanes, which are exactly
                // the (lane&3)==0 output-store lanes.
                sig[m][0] = dacc[m][0][0];
                sig[m][1] = dacc[m][0][2];
                __half* dm = den + m * 16 * LDD;
                *reinterpret_cast<uint32_t*>(dm + g * LDD + i2) =
                    h2u(dacc[m][0][0], dacc[m][0][1]);
                *reinterpret_cast<uint32_t*>(dm + (g + 8) * LDD + i2) =
                    h2u(dacc[m][0][2], dacc[m][0][3]);
                *reinterpret_cast<uint32_t*>(dm + g * LDD + i2 + 8) =
                    h2u(dacc[m][1][0], dacc[m][1][1]);
                *reinterpret_cast<uint32_t*>(dm + (g + 8) * LDD + i2 + 8) =
                    h2u(dacc[m][1][2], dacc[m][1][3]);
            }
        }
        __syncwarp();

        // ---- c0 input: k-tile0 = sh (gmem), k-tile1 = shifted density ----
        {
            __half z = __float2half(0.0f);
#pragma unroll
            for (int m = 0; m < MT; m++) {
                const float2* s0 =
                    reinterpret_cast<const float2*>(sh + (row0 + m * 16 + g) * 16);
                const float2* s8 =
                    reinterpret_cast<const float2*>(sh + (row0 + m * 16 + g + 8) * 16);
                float2 v0 = __ldcs(s0 + (i2 >> 1));
                float2 v1 = __ldcs(s8 + (i2 >> 1));
                float2 v2 = __ldcs(s0 + 4 + (i2 >> 1));
                float2 v3 = __ldcs(s8 + 4 + (i2 >> 1));
                Ab[m][0][0] = h2u(v0.x, v0.y);
                Ab[m][0][1] = h2u(v1.x, v1.y);
                Ab[m][0][2] = h2u(v2.x, v2.y);
                Ab[m][0][3] = h2u(v3.x, v3.y);
                const __half* dm = den + m * 16 * LDD;
                // concat col 16+j = d1 col j+1 (shift by one); col 31 -> 0
                __half hiA = (i2 == 6) ? z : dm[g * LDD + i2 + 10];
                __half hiB = (i2 == 6) ? z : dm[(g + 8) * LDD + i2 + 10];
                Ab[m][1][0] = hh2u(dm[g * LDD + i2 + 1],       dm[g * LDD + i2 + 2]);
                Ab[m][1][1] = hh2u(dm[(g + 8) * LDD + i2 + 1], dm[(g + 8) * LDD + i2 + 2]);
                Ab[m][1][2] = hh2u(dm[g * LDD + i2 + 9],       hiA);
                Ab[m][1][3] = hh2u(dm[(g + 8) * LDD + i2 + 9], hiB);
            }
        }

        // ---- c0, c1, c2 ----
        layer_chain<2, 4>(Ab, pw_c0, Aa);
        layer_chain<4, 4>(Aa, pw_c1, Ab);
        layer_chain<4, 4>(Ab, pw_c2, Aa);

        // ---- prefetch next tile's hash into Ab[m][0..1] (dead after c2) ----
        const int next = tile + gridDim.x;
        if (next < n_tiles)
            load_hash(Ab, hash, (size_t)next * CTA_M + warp * WARP_M, g, i2);

        // ---- c3: color (cols 0..2 of one 8-wide n-tile) ----
        {
            float cacc[MT][4];
#pragma unroll
            for (int m = 0; m < MT; m++)
#pragma unroll
                for (int e = 0; e < 4; e++) cacc[m][e] = 0.0f;
#pragma unroll
            for (int c = 0; c < 2; c++) {
                uint4 v = pw_c3[c * 32];
#pragma unroll
                for (int m = 0; m < MT; m++) {
                    mma16816(cacc[m], Aa[m][2 * c],     v.x, v.y);
                    mma16816(cacc[m], Aa[m][2 * c + 1], v.z, v.w);
                }
            }
#pragma unroll
            for (int m = 0; m < MT; m++) {
                // lane 4g holds cols {0,1}; lane 4g+1 holds col 2
                float b0c = __shfl_down_sync(0xffffffffu, cacc[m][0], 1);
                float b1c = __shfl_down_sync(0xffffffffu, cacc[m][2], 1);
                if ((lane & 3) == 0) {
                    out4[row0 + m * 16 + g] =
                        make_float4(cacc[m][0], cacc[m][1], b0c, sig[m][0]);
                    out4[row0 + m * 16 + g + 8] =
                        make_float4(cacc[m][2], cacc[m][3], b1c, sig[m][1]);
                }
            }
        }
        __syncwarp();  // den reads (this tile) before den writes (next tile)
        tile = next;
    }
}

extern "C" void kernel_launch(void* const* d_in, const int* in_sizes, int n_in,
                              void* d_out, int out_size) {
    const float* hash = (const float*)d_in[0];  // [N, 32]
    const float* sh   = (const float*)d_in[1];  // [N, 16]
    const float* d0   = (const float*)d_in[2];  // [64, 32]
    const float* d1   = (const float*)d_in[3];  // [16, 64]
    const float* c0   = (const float*)d_in[4];  // [64, 31]
    const float* c1   = (const float*)d_in[5];  // [64, 64]
    const float* c2   = (const float*)d_in[6];  // [64, 64]
    const float* c3   = (const float*)d_in[7];  // [3, 64]
    float* out = (float*)d_out;                 // [N, 4]

    const int n       = in_sizes[0] / 32;
    const int n_tiles = n / CTA_M;  // 16384

    int grid = 148 * 5;  // persistent, 5 CTAs/SM, 20 warps/SM
    if (grid > n_tiles) grid = n_tiles;

    nerf_fused_kernel<<<grid, THREADS>>>(hash, sh, d0, d1, c0, c1, c2, c3, out,
                                         n_tiles);
}

// round 10
// speedup vs baseline: 1.0914x; 1.0914x over previous
#include <cuda_runtime.h>
#include <cuda_fp16.h>
#include <cstdint>

namespace {

constexpr int THREADS = 128;             // 4 warps/CTA, 5 CTAs/SM -> 20 warps
constexpr int MT      = 2;               // 16-row m-tiles per warp
constexpr int WARP_M  = 16 * MT;         // 32 rows / warp
constexpr int NWARP   = 4;
constexpr int CTA_M   = NWARP * WARP_M;  // 128 rows / CTA

// Per-lane permuted weight tables: entry (nph, c, lane) = uint4 holding the
// (b0,b1) B-fragment pairs for k-tiles 2c, 2c+1 of n-group nph, as consumed by
// lane `lane`. 16B lane stride -> conflict-free LDS.128.
struct SmemLayout {
    uint4 p_d0[8 * 1 * 32];
    uint4 p_c0[8 * 1 * 32];
    uint4 p_d1[2 * 2 * 32];
    uint4 p_c1[8 * 2 * 32];
    uint4 p_c2[8 * 2 * 32];
    uint4 p_c3[1 * 2 * 32];
};  // 27 KB -> 5 CTAs/SM easily

__device__ __forceinline__ uint32_t h2u(float x, float y) {
    __half2 h = __floats2half2_rn(x, y);
    return *reinterpret_cast<uint32_t*>(&h);
}
__device__ __forceinline__ uint32_t relu2(uint32_t p) {
    __half2 h = *reinterpret_cast<__half2*>(&p);
    __half2 r = __hmax2(h, __half2(__float2half_rn(0.f), __float2half_rn(0.f)));
    return *reinterpret_cast<uint32_t*>(&r);
}

__device__ __forceinline__ void mma16816(float c[4], const uint32_t a[4],
                                         uint32_t b0, uint32_t b1) {
    asm volatile(
        "mma.sync.aligned.m16n8k16.row.col.f32.f16.f16.f32 "
        "{%0,%1,%2,%3},{%4,%5,%6,%7},{%8,%9},{%0,%1,%2,%3};\n"
        : "+f"(c[0]), "+f"(c[1]), "+f"(c[2]), "+f"(c[3])
        : "r"(a[0]), "r"(a[1]), "r"(a[2]), "r"(a[3]), "r"(b0), "r"(b1));
}

// Stage a [Nout x Kin] f32 row-major weight matrix into the permuted table.
__device__ void stage_perm(uint4* dst, const float* __restrict__ W, int Nout,
                           int Kin, int NPH, int CH, int tid) {
    const int total = NPH * CH * 32;
    for (int e = tid; e < total; e += THREADS) {
        int lane = e & 31;
        int c    = (e >> 5) % CH;
        int nph  = e / (32 * CH);
        int row  = (nph >> 1) * 16 + (nph & 1) * 8 + (lane >> 2);
        int col  = (lane & 3) * 2;
        int k0   = c * 32;
        auto rd = [&](int cc) -> float {
            return (row < Nout && cc < Kin) ? W[row * Kin + cc] : 0.0f;
        };
        uint4 v;
        v.x = h2u(rd(k0 + col),          rd(k0 + col + 1));
        v.y = h2u(rd(k0 + col + 8),      rd(k0 + col + 9));
        v.z = h2u(rd(k0 + 16 + col),     rd(k0 + 16 + col + 1));
        v.w = h2u(rd(k0 + 16 + col + 8), rd(k0 + 16 + col + 9));
        dst[e] = v;
    }
}

// Register-chained relu layer: one LDS.128 per (np,h,chunk) feeds 2*MT HMMAs.
template <int KT, int NP>
__device__ __forceinline__ void layer_chain(const uint32_t (&A)[MT][4][4],
                                            const uint4* __restrict__ pw,
                                            uint32_t (&O)[MT][4][4]) {
    constexpr int CH = KT / 2;
#pragma unroll
    for (int np = 0; np < NP; np++) {
        float acc[MT][2][4];
#pragma unroll
        for (int m = 0; m < MT; m++)
#pragma unroll
            for (int h = 0; h < 2; h++)
#pragma unroll
                for (int e = 0; e < 4; e++) acc[m][h][e] = 0.0f;
#pragma unroll
        for (int h = 0; h < 2; h++) {
#pragma unroll
            for (int c = 0; c < CH; c++) {
                uint4 v = pw[((np * 2 + h) * CH + c) * 32];
#pragma unroll
                for (int m = 0; m < MT; m++) {
                    mma16816(acc[m][h], A[m][2 * c],     v.x, v.y);
                    mma16816(acc[m][h], A[m][2 * c + 1], v.z, v.w);
                }
            }
        }
#pragma unroll
        for (int m = 0; m < MT; m++) {
            O[m][np][0] = relu2(h2u(acc[m][0][0], acc[m][0][1]));
            O[m][np][1] = relu2(h2u(acc[m][0][2], acc[m][0][3]));
            O[m][np][2] = relu2(h2u(acc[m][1][0], acc[m][1][1]));
            O[m][np][3] = relu2(h2u(acc[m][1][2], acc[m][1][3]));
        }
    }
}

}  // namespace

__global__ void __launch_bounds__(THREADS, 5)
nerf_fused_kernel(const float* __restrict__ hash, const float* __restrict__ sh,
                  const float* __restrict__ d0, const float* __restrict__ d1,
                  const float* __restrict__ c0, const float* __restrict__ c1,
                  const float* __restrict__ c2, const float* __restrict__ c3,
                  float* __restrict__ out, int n_tiles) {
    __shared__ SmemLayout S;
    const int tid  = threadIdx.x;
    const int warp = tid >> 5;
    const int lane = tid & 31;
    const int g    = lane >> 2;       // row-in-tile-half
    const int i2   = (lane & 3) * 2;  // column pair base

    // ---- Stage permuted weights once per CTA ----
    stage_perm(S.p_d0, d0, 64, 32, 8, 1, tid);
    stage_perm(S.p_c0, c0, 64, 31, 8, 1, tid);
    stage_perm(S.p_d1, d1, 16, 64, 2, 2, tid);
    stage_perm(S.p_c1, c1, 64, 64, 8, 2, tid);
    stage_perm(S.p_c2, c2, 64, 64, 8, 2, tid);
    stage_perm(S.p_c3, c3,  3, 64, 1, 2, tid);
    __syncthreads();  // only block barrier

    const uint4* pw_d0 = S.p_d0 + lane;
    const uint4* pw_c0 = S.p_c0 + lane;
    const uint4* pw_d1 = S.p_d1 + lane;
    const uint4* pw_c1 = S.p_c1 + lane;
    const uint4* pw_c2 = S.p_c2 + lane;
    const uint4* pw_c3 = S.p_c3 + lane;
    float4* out4 = reinterpret_cast<float4*>(out);
    const bool edge = (lane & 3) == 3;  // i2 == 6
    const unsigned FULL = 0xffffffffu;

    for (int tile = blockIdx.x; tile < n_tiles; tile += gridDim.x) {
        const size_t row0 = (size_t)tile * CTA_M + warp * WARP_M;

        uint32_t Aa[MT][4][4];  // ping
        uint32_t Ab[MT][4][4];  // pong; Ab[m][0..1] doubles as 32-wide input

        // ---- hash A frags straight from gmem (streaming) ----
#pragma unroll
        for (int m = 0; m < MT; m++) {
            const float2* h0 =
                reinterpret_cast<const float2*>(hash + (row0 + m * 16 + g) * 32);
            const float2* h8 =
                reinterpret_cast<const float2*>(hash + (row0 + m * 16 + g + 8) * 32);
#pragma unroll
            for (int kt = 0; kt < 2; kt++) {
                float2 v0 = __ldcs(h0 + kt * 8 + (i2 >> 1));
                float2 v1 = __ldcs(h8 + kt * 8 + (i2 >> 1));
                float2 v2 = __ldcs(h0 + kt * 8 + 4 + (i2 >> 1));
                float2 v3 = __ldcs(h8 + kt * 8 + 4 + (i2 >> 1));
                Ab[m][kt][0] = h2u(v0.x, v0.y);
                Ab[m][kt][1] = h2u(v1.x, v1.y);
                Ab[m][kt][2] = h2u(v2.x, v2.y);
                Ab[m][kt][3] = h2u(v3.x, v3.y);
            }
        }

        // ---- d0: relu(hash @ d0^T) ----
        layer_chain<2, 4>(Ab, pw_d0, Aa);

        // ---- d1: h @ d1^T -> sigma (regs) + density A-frag via shuffles ----
        float sig[MT][2];
#pragma unroll
        for (int m = 0; m < MT; m++) {
            float dacc[2][4];
#pragma unroll
            for (int h = 0; h < 2; h++)
#pragma unroll
                for (int e = 0; e < 4; e++) dacc[h][e] = 0.0f;
#pragma unroll
            for (int h = 0; h < 2; h++) {
#pragma unroll
                for (int c = 0; c < 2; c++) {
                    uint4 v = pw_d1[(h * 2 + c) * 32];
                    mma16816(dacc[h], Aa[m][2 * c],     v.x, v.y);
                    mma16816(dacc[h], Aa[m][2 * c + 1], v.z, v.w);
                }
            }
            // sigma = D col 0 (meaningful on (lane&3)==0 = output lanes)
            sig[m][0] = dacc[0][0];
            sig[m][1] = dacc[0][2];
            // Density shift-by-one: A1[r][j] = D[r][j+1] (j<15), A1[r][15]=0.
            // D[r][i2+2]  -> lane+1's dacc[0][*]; edge (i2==6): lane 4g's dacc[1][*]
            // D[r][i2+10] -> lane+1's dacc[1][*]; edge: col 15 -> 0
            float x00 = __shfl_sync(FULL, dacc[0][0], lane + 1);
            float x02 = __shfl_sync(FULL, dacc[0][2], lane + 1);
            float x10 = __shfl_sync(FULL, dacc[1][0], lane + 1);
            float x12 = __shfl_sync(FULL, dacc[1][2], lane + 1);
            float y10 = __shfl_sync(FULL, dacc[1][0], lane & ~3);
            float y12 = __shfl_sync(FULL, dacc[1][2], lane & ~3);
            float X0 = edge ? y10 : x00;
            float X1 = edge ? y12 : x02;
            float X2 = edge ? 0.f : x10;
            float X3 = edge ? 0.f : x12;
            Ab[m][1][0] = h2u(dacc[0][1], X0);  // (row g,   cols i2..i2+1)
            Ab[m][1][1] = h2u(dacc[0][3], X1);  // (row g+8)
            Ab[m][1][2] = h2u(dacc[1][1], X2);  // (row g,   cols i2+8..i2+9)
            Ab[m][1][3] = h2u(dacc[1][3], X3);  // (row g+8)
        }

        // ---- c0 input k-tile0 = sh (gmem) ----
#pragma unroll
        for (int m = 0; m < MT; m++) {
            const float2* s0 =
                reinterpret_cast<const float2*>(sh + (row0 + m * 16 + g) * 16);
            const float2* s8 =
                reinterpret_cast<const float2*>(sh + (row0 + m * 16 + g + 8) * 16);
            float2 v0 = __ldcs(s0 + (i2 >> 1));
            float2 v1 = __ldcs(s8 + (i2 >> 1));
            float2 v2 = __ldcs(s0 + 4 + (i2 >> 1));
            float2 v3 = __ldcs(s8 + 4 + (i2 >> 1));
            Ab[m][0][0] = h2u(v0.x, v0.y);
            Ab[m][0][1] = h2u(v1.x, v1.y);
            Ab[m][0][2] = h2u(v2.x, v2.y);
            Ab[m][0][3] = h2u(v3.x, v3.y);
        }

        // ---- c0, c1, c2 ----
        layer_chain<2, 4>(Ab, pw_c0, Aa);
        layer_chain<4, 4>(Aa, pw_c1, Ab);
        layer_chain<4, 4>(Ab, pw_c2, Aa);

        // ---- c3: color (cols 0..2 of one 8-wide n-tile) ----
        {
            float cacc[MT][4];
#pragma unroll
            for (int m = 0; m < MT; m++)
#pragma unroll
                for (int e = 0; e < 4; e++) cacc[m][e] = 0.0f;
#pragma unroll
            for (int c = 0; c < 2; c++) {
                uint4 v = pw_c3[c * 32];
#pragma unroll
                for (int m = 0; m < MT; m++) {
                    mma16816(cacc[m], Aa[m][2 * c],     v.x, v.y);
                    mma16816(cacc[m], Aa[m][2 * c + 1], v.z, v.w);
                }
            }
#pragma unroll
            for (int m = 0; m < MT; m++) {
                // lane 4g holds cols {0,1}; lane 4g+1 holds col 2
                float b0c = __shfl_down_sync(FULL, cacc[m][0], 1);
                float b1c = __shfl_down_sync(FULL, cacc[m][2], 1);
                if ((lane & 3) == 0) {
                    out4[row0 + m * 16 + g] =
                        make_float4(cacc[m][0], cacc[m][1], b0c, sig[m][0]);
                    out4[row0 + m * 16 + g + 8] =
                        make_float4(cacc[m][2], cacc[m][3], b1c, sig[m][1]);
                }
            }
        }
    }
}

extern "C" void kernel_launch(void* const* d_in, const int* in_sizes, int n_in,
                              void* d_out, int out_size) {
    const float* hash = (const float*)d_in[0];  // [N, 32]
    const float* sh   = (const float*)d_in[1];  // [N, 16]
    const float* d0   = (const float*)d_in[2];  // [64, 32]
    const float* d1   = (const float*)d_in[3];  // [16, 64]
    const float* c0   = (const float*)d_in[4];  // [64, 31]
    const float* c1   = (const float*)d_in[5];  // [64, 64]
    const float* c2   = (const float*)d_in[6];  // [64, 64]
    const float* c3   = (const float*)d_in[7];  // [3, 64]
    float* out = (float*)d_out;                 // [N, 4]

    const int n       = in_sizes[0] / 32;
    const int n_tiles = n / CTA_M;  // 16384

    int grid = 148 * 5;  // persistent, 5 CTAs/SM, 20 warps/SM
    if (grid > n_tiles) grid = n_tiles;

    nerf_fused_kernel<<<grid, THREADS>>>(hash, sh, d0, d1, c0, c1, c2, c3, out,
                                         n_tiles);
}

// round 11
// speedup vs baseline: 1.1387x; 1.0433x over previous
#include <cuda_runtime.h>
#include <cuda_fp16.h>
#include <cstdint>

namespace {

constexpr int THREADS = 128;             // 4 warps/CTA, 5 CTAs/SM -> 20 warps
constexpr int MT      = 2;               // 16-row m-tiles per warp
constexpr int WARP_M  = 16 * MT;         // 32 rows / warp
constexpr int NWARP   = 4;
constexpr int CTA_M   = NWARP * WARP_M;  // 128 rows / CTA

// Per-lane permuted weight tables: entry (nph, c, lane) = uint4 holding the
// (b0,b1) B-fragment pairs for k-tiles 2c, 2c+1 of n-group nph, as consumed by
// lane `lane`. 16B lane stride -> conflict-free LDS.128.
struct SmemLayout {
    uint4 p_d0[8 * 1 * 32];
    uint4 p_c0[8 * 1 * 32];
    uint4 p_d1[2 * 2 * 32];
    uint4 p_c1[8 * 2 * 32];
    uint4 p_c2[8 * 2 * 32];
    uint4 p_c3[1 * 2 * 32];
};  // 27 KB

__device__ __forceinline__ uint32_t h2u(float x, float y) {
    __half2 h = __floats2half2_rn(x, y);
    return *reinterpret_cast<uint32_t*>(&h);
}
__device__ __forceinline__ uint32_t relu2(uint32_t p) {
    __half2 h = *reinterpret_cast<__half2*>(&p);
    __half2 r = __hmax2(h, __half2(__float2half_rn(0.f), __float2half_rn(0.f)));
    return *reinterpret_cast<uint32_t*>(&r);
}

__device__ __forceinline__ void mma16816(float c[4], const uint32_t a[4],
                                         uint32_t b0, uint32_t b1) {
    asm volatile(
        "mma.sync.aligned.m16n8k16.row.col.f32.f16.f16.f32 "
        "{%0,%1,%2,%3},{%4,%5,%6,%7},{%8,%9},{%0,%1,%2,%3};\n"
        : "+f"(c[0]), "+f"(c[1]), "+f"(c[2]), "+f"(c[3])
        : "r"(a[0]), "r"(a[1]), "r"(a[2]), "r"(a[3]), "r"(b0), "r"(b1));
}

// Stage a [Nout x Kin] f32 row-major weight matrix into the permuted table.
// permMask bit kt: k-tile kt uses the gmem-contiguous K-permutation
// (mma-cols (2q,2q+1)->(4q,4q+1), (2q+8,2q+9)->(4q+2,4q+3)); else identity.
__device__ void stage_perm(uint4* dst, const float* __restrict__ W, int Nout,
                           int Kin, int NPH, int CH, int permMask, int tid) {
    const int total = NPH * CH * 32;
    for (int e = tid; e < total; e += THREADS) {
        int lane = e & 31;
        int c    = (e >> 5) % CH;
        int nph  = e / (32 * CH);
        int row  = (nph >> 1) * 16 + (nph & 1) * 8 + (lane >> 2);
        int q    = lane & 3;
        auto rd = [&](int cc) -> float {
            return (row < Nout && cc < Kin) ? W[row * Kin + cc] : 0.0f;
        };
        auto pack = [&](int kt, int half) -> uint32_t {
            int base = kt * 16;
            int c0 = (permMask >> kt) & 1 ? base + 4 * q + (half ? 2 : 0)
                                          : base + 2 * q + (half ? 8 : 0);
            return h2u(rd(c0), rd(c0 + 1));
        };
        uint4 v;
        v.x = pack(2 * c,     0);
        v.y = pack(2 * c,     1);
        v.z = pack(2 * c + 1, 0);
        v.w = pack(2 * c + 1, 1);
        dst[e] = v;
    }
}

// Register-chained relu layer: one LDS.128 per (np,h,chunk) feeds 2*MT HMMAs.
template <int KT, int NP>
__device__ __forceinline__ void layer_chain(const uint32_t (&A)[MT][4][4],
                                            const uint4* __restrict__ pw,
                                            uint32_t (&O)[MT][4][4]) {
    constexpr int CH = KT / 2;
#pragma unroll
    for (int np = 0; np < NP; np++) {
        float acc[MT][2][4];
#pragma unroll
        for (int m = 0; m < MT; m++)
#pragma unroll
            for (int h = 0; h < 2; h++)
#pragma unroll
                for (int e = 0; e < 4; e++) acc[m][h][e] = 0.0f;
#pragma unroll
        for (int h = 0; h < 2; h++) {
#pragma unroll
            for (int c = 0; c < CH; c++) {
                uint4 v = pw[((np * 2 + h) * CH + c) * 32];
#pragma unroll
                for (int m = 0; m < MT; m++) {
                    mma16816(acc[m][h], A[m][2 * c],     v.x, v.y);
                    mma16816(acc[m][h], A[m][2 * c + 1], v.z, v.w);
                }
            }
        }
#pragma unroll
        for (int m = 0; m < MT; m++) {
            O[m][np][0] = relu2(h2u(acc[m][0][0], acc[m][0][1]));
            O[m][np][1] = relu2(h2u(acc[m][0][2], acc[m][0][3]));
            O[m][np][2] = relu2(h2u(acc[m][1][0], acc[m][1][1]));
            O[m][np][3] = relu2(h2u(acc[m][1][2], acc[m][1][3]));
        }
    }
}

}  // namespace

__global__ void __launch_bounds__(THREADS, 5)
nerf_fused_kernel(const float* __restrict__ hash, const float* __restrict__ sh,
                  const float* __restrict__ d0, const float* __restrict__ d1,
                  const float* __restrict__ c0, const float* __restrict__ c1,
                  const float* __restrict__ c2, const float* __restrict__ c3,
                  float* __restrict__ out, int n_tiles) {
    __shared__ SmemLayout S;
    const int tid  = threadIdx.x;
    const int warp = tid >> 5;
    const int lane = tid & 31;
    const int g    = lane >> 2;   // row-in-tile-half
    const int q    = lane & 3;    // column group

    // ---- Stage permuted weights once per CTA ----
    stage_perm(S.p_d0, d0, 64, 32, 8, 1, 0b11, tid);  // hash input: both k-tiles permuted
    stage_perm(S.p_c0, c0, 64, 31, 8, 1, 0b01, tid);  // sh k-tile permuted, density identity
    stage_perm(S.p_d1, d1, 16, 64, 2, 2, 0, tid);
    stage_perm(S.p_c1, c1, 64, 64, 8, 2, 0, tid);
    stage_perm(S.p_c2, c2, 64, 64, 8, 2, 0, tid);
    stage_perm(S.p_c3, c3,  3, 64, 1, 2, 0, tid);
    __syncthreads();  // only block barrier

    const uint4* pw_d0 = S.p_d0 + lane;
    const uint4* pw_c0 = S.p_c0 + lane;
    const uint4* pw_d1 = S.p_d1 + lane;
    const uint4* pw_c1 = S.p_c1 + lane;
    const uint4* pw_c2 = S.p_c2 + lane;
    const uint4* pw_c3 = S.p_c3 + lane;
    float4* out4 = reinterpret_cast<float4*>(out);
    const float4* hash4 = reinterpret_cast<const float4*>(hash);  // row = 8 f4
    const float4* sh4   = reinterpret_cast<const float4*>(sh);    // row = 4 f4
    const bool edge = (q == 3);
    const unsigned FULL = 0xffffffffu;

    for (int tile = blockIdx.x; tile < n_tiles; tile += gridDim.x) {
        const size_t row0 = (size_t)tile * CTA_M + warp * WARP_M;

        uint32_t Aa[MT][4][4];  // ping
        uint32_t Ab[MT][4][4];  // pong; Ab[m][0..1] doubles as 32-wide input

        // ---- hash A frags: one LDG.128 per row-half per k-tile (K-perm) ----
#pragma unroll
        for (int m = 0; m < MT; m++) {
#pragma unroll
            for (int kt = 0; kt < 2; kt++) {
                float4 v0 = __ldcs(hash4 + (row0 + m * 16 + g) * 8 + kt * 4 + q);
                float4 v1 = __ldcs(hash4 + (row0 + m * 16 + g + 8) * 8 + kt * 4 + q);
                Ab[m][kt][0] = h2u(v0.x, v0.y);
                Ab[m][kt][1] = h2u(v1.x, v1.y);
                Ab[m][kt][2] = h2u(v0.z, v0.w);
                Ab[m][kt][3] = h2u(v1.z, v1.w);
            }
        }

        // ---- d0: relu(hash @ d0^T) ----
        layer_chain<2, 4>(Ab, pw_d0, Aa);

        // ---- sh loads issued NOW (into dead Ab[m][0]); d1 hides the latency
#pragma unroll
        for (int m = 0; m < MT; m++) {
            float4 v0 = __ldcs(sh4 + (row0 + m * 16 + g) * 4 + q);
            float4 v1 = __ldcs(sh4 + (row0 + m * 16 + g + 8) * 4 + q);
            Ab[m][0][0] = h2u(v0.x, v0.y);
            Ab[m][0][1] = h2u(v1.x, v1.y);
            Ab[m][0][2] = h2u(v0.z, v0.w);
            Ab[m][0][3] = h2u(v1.z, v1.w);
        }

        // ---- d1: h @ d1^T -> sigma (regs) + density A-frag via shuffles ----
        float sig[MT][2];
#pragma unroll
        for (int m = 0; m < MT; m++) {
            float dacc[2][4];
#pragma unroll
            for (int h = 0; h < 2; h++)
#pragma unroll
                for (int e = 0; e < 4; e++) dacc[h][e] = 0.0f;
#pragma unroll
            for (int h = 0; h < 2; h++) {
#pragma unroll
                for (int c = 0; c < 2; c++) {
                    uint4 v = pw_d1[(h * 2 + c) * 32];
                    mma16816(dacc[h], Aa[m][2 * c],     v.x, v.y);
                    mma16816(dacc[h], Aa[m][2 * c + 1], v.z, v.w);
                }
            }
            // sigma = D col 0 (meaningful on q==0 = output lanes)
            sig[m][0] = dacc[0][0];
            sig[m][1] = dacc[0][2];
            // Density shift-by-one: A1[r][j] = D[r][j+1] (j<15), A1[r][15]=0.
            float x00 = __shfl_sync(FULL, dacc[0][0], lane + 1);
            float x02 = __shfl_sync(FULL, dacc[0][2], lane + 1);
            float x10 = __shfl_sync(FULL, dacc[1][0], lane + 1);
            float x12 = __shfl_sync(FULL, dacc[1][2], lane + 1);
            float y10 = __shfl_sync(FULL, dacc[1][0], lane & ~3);
            float y12 = __shfl_sync(FULL, dacc[1][2], lane & ~3);
            float X0 = edge ? y10 : x00;
            float X1 = edge ? y12 : x02;
            float X2 = edge ? 0.f : x10;
            float X3 = edge ? 0.f : x12;
            Ab[m][1][0] = h2u(dacc[0][1], X0);
            Ab[m][1][1] = h2u(dacc[0][3], X1);
            Ab[m][1][2] = h2u(dacc[1][1], X2);
            Ab[m][1][3] = h2u(dacc[1][3], X3);
        }

        // ---- c0, c1, c2 ----
        layer_chain<2, 4>(Ab, pw_c0, Aa);
        layer_chain<4, 4>(Aa, pw_c1, Ab);
        layer_chain<4, 4>(Ab, pw_c2, Aa);

        // ---- c3: color (cols 0..2 of one 8-wide n-tile) ----
        {
            float cacc[MT][4];
#pragma unroll
            for (int m = 0; m < MT; m++)
#pragma unroll
                for (int e = 0; e < 4; e++) cacc[m][e] = 0.0f;
#pragma unroll
            for (int c = 0; c < 2; c++) {
                uint4 v = pw_c3[c * 32];
#pragma unroll
                for (int m = 0; m < MT; m++) {
                    mma16816(cacc[m], Aa[m][2 * c],     v.x, v.y);
                    mma16816(cacc[m], Aa[m][2 * c + 1], v.z, v.w);
                }
            }
#pragma unroll
            for (int m = 0; m < MT; m++) {
                // lane 4g holds cols {0,1}; lane 4g+1 holds col 2
                float b0c = __shfl_down_sync(FULL, cacc[m][0], 1);
                float b1c = __shfl_down_sync(FULL, cacc[m][2], 1);
                if (q == 0) {
                    out4[row0 + m * 16 + g] =
                        make_float4(cacc[m][0], cacc[m][1], b0c, sig[m][0]);
                    out4[row0 + m * 16 + g + 8] =
                        make_float4(cacc[m][2], cacc[m][3], b1c, sig[m][1]);
                }
            }
        }
    }
}

extern "C" void kernel_launch(void* const* d_in, const int* in_sizes, int n_in,
                              void* d_out, int out_size) {
    const float* hash = (const float*)d_in[0];  // [N, 32]
    const float* sh   = (const float*)d_in[1];  // [N, 16]
    const float* d0   = (const float*)d_in[2];  // [64, 32]
    const float* d1   = (const float*)d_in[3];  // [16, 64]
    const float* c0   = (const float*)d_in[4];  // [64, 31]
    const float* c1   = (const float*)d_in[5];  // [64, 64]
    const float* c2   = (const float*)d_in[6];  // [64, 64]
    const float* c3   = (const float*)d_in[7];  // [3, 64]
    float* out = (float*)d_out;                 // [N, 4]

    const int n       = in_sizes[0] / 32;
    const int n_tiles = n / CTA_M;  // 16384

    int grid = 148 * 5;  // persistent, 5 CTAs/SM, 20 warps/SM
    if (grid > n_tiles) grid = n_tiles;

    nerf_fused_kernel<<<grid, THREADS>>>(hash, sh, d0, d1, c0, c1, c2, c3, out,
                                         n_tiles);
}

// round 12
// speedup vs baseline: 1.1574x; 1.0165x over previous
#include <cuda_runtime.h>
#include <cuda_fp16.h>
#include <cstdint>

namespace {

constexpr int THREADS = 128;             // 4 warps/CTA, 5 CTAs/SM -> 20 warps
constexpr int MT      = 2;               // 16-row m-tiles per warp
constexpr int WARP_M  = 16 * MT;         // 32 rows / warp
constexpr int NWARP   = 4;
constexpr int CTA_M   = NWARP * WARP_M;  // 128 rows / CTA

// Per-lane permuted weight tables: entry (nph, c, lane) = uint4 holding the
// (b0,b1) B-fragment pairs for k-tiles 2c, 2c+1 of n-group nph, as consumed by
// lane `lane`. 16B lane stride -> conflict-free LDS.128.
struct SmemLayout {
    uint4 p_d0[8 * 1 * 32];
    uint4 p_c0[8 * 1 * 32];
    uint4 p_d1[2 * 2 * 32];
    uint4 p_c1[8 * 2 * 32];
    uint4 p_c2[8 * 2 * 32];
    uint4 p_c3[1 * 2 * 32];
};  // 27 KB

__device__ __forceinline__ uint32_t h2u(float x, float y) {
    __half2 h = __floats2half2_rn(x, y);
    return *reinterpret_cast<uint32_t*>(&h);
}
// Fused relu + pack: lo = relu(rn(x)), hi = relu(rn(y)). One SASS op.
__device__ __forceinline__ uint32_t cvt_relu2(float x, float y) {
    uint32_t r;
    asm("cvt.rn.relu.f16x2.f32 %0, %1, %2;\n" : "=r"(r) : "f"(y), "f"(x));
    return r;
}

__device__ __forceinline__ void mma16816(float c[4], const uint32_t a[4],
                                         uint32_t b0, uint32_t b1) {
    asm volatile(
        "mma.sync.aligned.m16n8k16.row.col.f32.f16.f16.f32 "
        "{%0,%1,%2,%3},{%4,%5,%6,%7},{%8,%9},{%0,%1,%2,%3};\n"
        : "+f"(c[0]), "+f"(c[1]), "+f"(c[2]), "+f"(c[3])
        : "r"(a[0]), "r"(a[1]), "r"(a[2]), "r"(a[3]), "r"(b0), "r"(b1));
}

// Stage a [Nout x Kin] f32 row-major weight matrix into the permuted table.
// permMask bit kt: k-tile kt uses the gmem-contiguous K-permutation
// (mma-cols (2q,2q+1)->(4q,4q+1), (2q+8,2q+9)->(4q+2,4q+3)); else identity.
__device__ void stage_perm(uint4* dst, const float* __restrict__ W, int Nout,
                           int Kin, int NPH, int CH, int permMask, int tid) {
    const int total = NPH * CH * 32;
    for (int e = tid; e < total; e += THREADS) {
        int lane = e & 31;
        int c    = (e >> 5) % CH;
        int nph  = e / (32 * CH);
        int row  = (nph >> 1) * 16 + (nph & 1) * 8 + (lane >> 2);
        int q    = lane & 3;
        auto rd = [&](int cc) -> float {
            return (row < Nout && cc < Kin) ? W[row * Kin + cc] : 0.0f;
        };
        auto pack = [&](int kt, int half) -> uint32_t {
            int base = kt * 16;
            int c0 = (permMask >> kt) & 1 ? base + 4 * q + (half ? 2 : 0)
                                          : base + 2 * q + (half ? 8 : 0);
            return h2u(rd(c0), rd(c0 + 1));
        };
        uint4 v;
        v.x = pack(2 * c,     0);
        v.y = pack(2 * c,     1);
        v.z = pack(2 * c + 1, 0);
        v.w = pack(2 * c + 1, 1);
        dst[e] = v;
    }
}

// Register-chained relu layer: one LDS.128 per (np,h,chunk) feeds 2*MT HMMAs;
// epilogue is one fused cvt.relu per output register.
template <int KT, int NP>
__device__ __forceinline__ void layer_chain(const uint32_t (&A)[MT][4][4],
                                            const uint4* __restrict__ pw,
                                            uint32_t (&O)[MT][4][4]) {
    constexpr int CH = KT / 2;
#pragma unroll
    for (int np = 0; np < NP; np++) {
        float acc[MT][2][4];
#pragma unroll
        for (int m = 0; m < MT; m++)
#pragma unroll
            for (int h = 0; h < 2; h++)
#pragma unroll
                for (int e = 0; e < 4; e++) acc[m][h][e] = 0.0f;
#pragma unroll
        for (int h = 0; h < 2; h++) {
#pragma unroll
            for (int c = 0; c < CH; c++) {
                uint4 v = pw[((np * 2 + h) * CH + c) * 32];
#pragma unroll
                for (int m = 0; m < MT; m++) {
                    mma16816(acc[m][h], A[m][2 * c],     v.x, v.y);
                    mma16816(acc[m][h], A[m][2 * c + 1], v.z, v.w);
                }
            }
        }
#pragma unroll
        for (int m = 0; m < MT; m++) {
            O[m][np][0] = cvt_relu2(acc[m][0][0], acc[m][0][1]);
            O[m][np][1] = cvt_relu2(acc[m][0][2], acc[m][0][3]);
            O[m][np][2] = cvt_relu2(acc[m][1][0], acc[m][1][1]);
            O[m][np][3] = cvt_relu2(acc[m][1][2], acc[m][1][3]);
        }
    }
}

}  // namespace

__global__ void __launch_bounds__(THREADS, 5)
nerf_fused_kernel(const float* __restrict__ hash, const float* __restrict__ sh,
                  const float* __restrict__ d0, const float* __restrict__ d1,
                  const float* __restrict__ c0, const float* __restrict__ c1,
                  const float* __restrict__ c2, const float* __restrict__ c3,
                  float* __restrict__ out, int n_tiles) {
    __shared__ SmemLayout S;
    const int tid  = threadIdx.x;
    const int warp = tid >> 5;
    const int lane = tid & 31;
    const int g    = lane >> 2;   // row-in-tile-half
    const int q    = lane & 3;    // column group

    // ---- Stage permuted weights once per CTA ----
    stage_perm(S.p_d0, d0, 64, 32, 8, 1, 0b11, tid);  // hash input: both k-tiles permuted
    stage_perm(S.p_c0, c0, 64, 31, 8, 1, 0b01, tid);  // sh k-tile permuted, density identity
    stage_perm(S.p_d1, d1, 16, 64, 2, 2, 0, tid);
    stage_perm(S.p_c1, c1, 64, 64, 8, 2, 0, tid);
    stage_perm(S.p_c2, c2, 64, 64, 8, 2, 0, tid);
    stage_perm(S.p_c3, c3,  3, 64, 1, 2, 0, tid);
    __syncthreads();  // only block barrier

    const uint4* pw_d0 = S.p_d0 + lane;
    const uint4* pw_c0 = S.p_c0 + lane;
    const uint4* pw_d1 = S.p_d1 + lane;
    const uint4* pw_c1 = S.p_c1 + lane;
    const uint4* pw_c2 = S.p_c2 + lane;
    const uint4* pw_c3 = S.p_c3 + lane;
    float4* out4 = reinterpret_cast<float4*>(out);
    const float4* hash4 = reinterpret_cast<const float4*>(hash);  // row = 8 f4
    const float4* sh4   = reinterpret_cast<const float4*>(sh);    // row = 4 f4
    const bool edge = (q == 3);
    const unsigned FULL = 0xffffffffu;

    for (int tile = blockIdx.x; tile < n_tiles; tile += gridDim.x) {
        const size_t row0 = (size_t)tile * CTA_M + warp * WARP_M;

        uint32_t Aa[MT][4][4];  // ping
        uint32_t Ab[MT][4][4];  // pong; Ab[m][0..1] doubles as 32-wide input

        // ---- hash A frags: one LDG.128 per row-half per k-tile (K-perm) ----
#pragma unroll
        for (int m = 0; m < MT; m++) {
#pragma unroll
            for (int kt = 0; kt < 2; kt++) {
                float4 v0 = __ldcs(hash4 + (row0 + m * 16 + g) * 8 + kt * 4 + q);
                float4 v1 = __ldcs(hash4 + (row0 + m * 16 + g + 8) * 8 + kt * 4 + q);
                Ab[m][kt][0] = h2u(v0.x, v0.y);
                Ab[m][kt][1] = h2u(v1.x, v1.y);
                Ab[m][kt][2] = h2u(v0.z, v0.w);
                Ab[m][kt][3] = h2u(v1.z, v1.w);
            }
        }

        // ---- d0: relu(hash @ d0^T) ----
        layer_chain<2, 4>(Ab, pw_d0, Aa);

        // ---- sh loads issued NOW (into dead Ab[m][0]); d1 hides the latency
#pragma unroll
        for (int m = 0; m < MT; m++) {
            float4 v0 = __ldcs(sh4 + (row0 + m * 16 + g) * 4 + q);
            float4 v1 = __ldcs(sh4 + (row0 + m * 16 + g + 8) * 4 + q);
            Ab[m][0][0] = h2u(v0.x, v0.y);
            Ab[m][0][1] = h2u(v1.x, v1.y);
            Ab[m][0][2] = h2u(v0.z, v0.w);
            Ab[m][0][3] = h2u(v1.z, v1.w);
        }

        // ---- d1: h @ d1^T -> sigma (regs) + density A-frag via shuffles ----
        float sig[MT][2];
#pragma unroll
        for (int m = 0; m < MT; m++) {
            float dacc[2][4];
#pragma unroll
            for (int h = 0; h < 2; h++)
#pragma unroll
                for (int e = 0; e < 4; e++) dacc[h][e] = 0.0f;
#pragma unroll
            for (int h = 0; h < 2; h++) {
#pragma unroll
                for (int c = 0; c < 2; c++) {
                    uint4 v = pw_d1[(h * 2 + c) * 32];
                    mma16816(dacc[h], Aa[m][2 * c],     v.x, v.y);
                    mma16816(dacc[h], Aa[m][2 * c + 1], v.z, v.w);
                }
            }
            // sigma = D col 0 (meaningful on q==0 = output lanes)
            sig[m][0] = dacc[0][0];
            sig[m][1] = dacc[0][2];
            // Density shift-by-one: A1[r][j] = D[r][j+1] (j<15), A1[r][15]=0.
            float x00 = __shfl_sync(FULL, dacc[0][0], lane + 1);
            float x02 = __shfl_sync(FULL, dacc[0][2], lane + 1);
            float x10 = __shfl_sync(FULL, dacc[1][0], lane + 1);
            float x12 = __shfl_sync(FULL, dacc[1][2], lane + 1);
            float y10 = __shfl_sync(FULL, dacc[1][0], lane & ~3);
            float y12 = __shfl_sync(FULL, dacc[1][2], lane & ~3);
            float X0 = edge ? y10 : x00;
            float X1 = edge ? y12 : x02;
            float X2 = edge ? 0.f : x10;
            float X3 = edge ? 0.f : x12;
            Ab[m][1][0] = h2u(dacc[0][1], X0);
            Ab[m][1][1] = h2u(dacc[0][3], X1);
            Ab[m][1][2] = h2u(dacc[1][1], X2);
            Ab[m][1][3] = h2u(dacc[1][3], X3);
        }

        // ---- c0, c1, c2 ----
        layer_chain<2, 4>(Ab, pw_c0, Aa);
        layer_chain<4, 4>(Aa, pw_c1, Ab);
        layer_chain<4, 4>(Ab, pw_c2, Aa);

        // ---- c3: color (cols 0..2 of one 8-wide n-tile) ----
        {
            float cacc[MT][4];
#pragma unroll
            for (int m = 0; m < MT; m++)
#pragma unroll
                for (int e = 0; e < 4; e++) cacc[m][e] = 0.0f;
#pragma unroll
            for (int c = 0; c < 2; c++) {
                uint4 v = pw_c3[c * 32];
#pragma unroll
                for (int m = 0; m < MT; m++) {
                    mma16816(cacc[m], Aa[m][2 * c],     v.x, v.y);
                    mma16816(cacc[m], Aa[m][2 * c + 1], v.z, v.w);
                }
            }
#pragma unroll
            for (int m = 0; m < MT; m++) {
                // lane 4g holds cols {0,1}; lane 4g+1 holds col 2
                float b0c = __shfl_down_sync(FULL, cacc[m][0], 1);
                float b1c = __shfl_down_sync(FULL, cacc[m][2], 1);
                if (q == 0) {
                    out4[row0 + m * 16 + g] =
                        make_float4(cacc[m][0], cacc[m][1], b0c, sig[m][0]);
                    out4[row0 + m * 16 + g + 8] =
                        make_float4(cacc[m][2], cacc[m][3], b1c, sig[m][1]);
                }
            }
        }
    }
}

extern "C" void kernel_launch(void* const* d_in, const int* in_sizes, int n_in,
                              void* d_out, int out_size) {
    const float* hash = (const float*)d_in[0];  // [N, 32]
    const float* sh   = (const float*)d_in[1];  // [N, 16]
    const float* d0   = (const float*)d_in[2];  // [64, 32]
    const float* d1   = (const float*)d_in[3];  // [16, 64]
    const float* c0   = (const float*)d_in[4];  // [64, 31]
    const float* c1   = (const float*)d_in[5];  // [64, 64]
    const float* c2   = (const float*)d_in[6];  // [64, 64]
    const float* c3   = (const float*)d_in[7];  // [3, 64]
    float* out = (float*)d_out;                 // [N, 4]

    const int n       = in_sizes[0] / 32;
    const int n_tiles = n / CTA_M;  // 16384

    int grid = 148 * 5;  // persistent, 5 CTAs/SM, 20 warps/SM
    if (grid > n_tiles) grid = n_tiles;

    nerf_fused_kernel<<<grid, THREADS>>>(hash, sh, d0, d1, c0, c1, c2, c3, out,
                                         n_tiles);
}

// round 13
// speedup vs baseline: 1.1605x; 1.0026x over previous
#include <cuda_runtime.h>
#include <cuda_fp16.h>
#include <cstdint>

namespace {

constexpr int THREADS = 128;             // 4 warps/CTA, 5 CTAs/SM -> 20 warps
constexpr int MT      = 2;               // 16-row m-tiles per warp
constexpr int WARP_M  = 16 * MT;         // 32 rows / warp
constexpr int NWARP   = 4;
constexpr int CTA_M   = NWARP * WARP_M;  // 128 rows / CTA

// Per-lane permuted weight tables: entry (nph, c, lane) = uint4 holding the
// (b0,b1) B-fragment pairs for k-tiles 2c, 2c+1 of n-group nph, as consumed by
// lane `lane`. 16B lane stride -> conflict-free LDS.128.
struct SmemLayout {
    uint4 p_d0[8 * 1 * 32];
    uint4 p_c0[8 * 1 * 32];
    uint4 p_d1[2 * 2 * 32];
    uint4 p_c1[8 * 2 * 32];
    uint4 p_c2[8 * 2 * 32];
    uint4 p_c3[1 * 2 * 32];
};  // 27 KB

__device__ __forceinline__ uint32_t h2u(float x, float y) {
    __half2 h = __floats2half2_rn(x, y);
    return *reinterpret_cast<uint32_t*>(&h);
}
// Fused relu + pack: lo = relu(rn(x)), hi = relu(rn(y)). One SASS op.
__device__ __forceinline__ uint32_t cvt_relu2(float x, float y) {
    uint32_t r;
    asm("cvt.rn.relu.f16x2.f32 %0, %1, %2;\n" : "=r"(r) : "f"(y), "f"(x));
    return r;
}

__device__ __forceinline__ void mma16816(float c[4], const uint32_t a[4],
                                         uint32_t b0, uint32_t b1) {
    asm volatile(
        "mma.sync.aligned.m16n8k16.row.col.f32.f16.f16.f32 "
        "{%0,%1,%2,%3},{%4,%5,%6,%7},{%8,%9},{%0,%1,%2,%3};\n"
        : "+f"(c[0]), "+f"(c[1]), "+f"(c[2]), "+f"(c[3])
        : "r"(a[0]), "r"(a[1]), "r"(a[2]), "r"(a[3]), "r"(b0), "r"(b1));
}

// Stage a [Nout x Kin] f32 row-major weight matrix into the permuted table.
// Per-k-tile mode (2 bits each in `modes`):
//   0 = identity        (mma-col t -> W col base + t)
//   1 = gmem K-perm     (cols (2q,2q+1)->(4q,4q+1), (2q+8,+9)->(4q+2,+3))
//   2 = density shift   (mma-col t -> W col 15+t; col 0 -> 0)  [c0 k-tile 1]
__device__ void stage_perm(uint4* dst, const float* __restrict__ W, int Nout,
                           int Kin, int NPH, int CH, int modes, int tid) {
    const int total = NPH * CH * 32;
    for (int e = tid; e < total; e += THREADS) {
        int lane = e & 31;
        int c    = (e >> 5) % CH;
        int nph  = e / (32 * CH);
        int row  = (nph >> 1) * 16 + (nph & 1) * 8 + (lane >> 2);
        int q    = lane & 3;
        auto rd = [&](int cc) -> float {
            return (cc >= 0 && row < Nout && cc < Kin) ? W[row * Kin + cc] : 0.0f;
        };
        auto pack = [&](int kt, int half) -> uint32_t {
            int mode = (modes >> (2 * kt)) & 3;
            int base = kt * 16;
            int t    = 2 * q + (half ? 8 : 0);  // identity mma column
            int ca, cb;
            if (mode == 1) {
                ca = base + 4 * q + (half ? 2 : 0);
                cb = ca + 1;
            } else if (mode == 2) {
                ca = (t == 0) ? -1 : 15 + t;  // col 0 (sigma) contributes 0
                cb = 15 + t + 1;
            } else {
                ca = base + t;
                cb = ca + 1;
            }
            return h2u(rd(ca), rd(cb));
        };
        uint4 v;
        v.x = pack(2 * c,     0);
        v.y = pack(2 * c,     1);
        v.z = pack(2 * c + 1, 0);
        v.w = pack(2 * c + 1, 1);
        dst[e] = v;
    }
}

// Register-chained relu layer: one LDS.128 per (np,h,chunk) feeds 2*MT HMMAs;
// epilogue is one fused cvt.relu per output register.
template <int KT, int NP>
__device__ __forceinline__ void layer_chain(const uint32_t (&A)[MT][4][4],
                                            const uint4* __restrict__ pw,
                                            uint32_t (&O)[MT][4][4]) {
    constexpr int CH = KT / 2;
#pragma unroll
    for (int np = 0; np < NP; np++) {
        float acc[MT][2][4];
#pragma unroll
        for (int m = 0; m < MT; m++)
#pragma unroll
            for (int h = 0; h < 2; h++)
#pragma unroll
                for (int e = 0; e < 4; e++) acc[m][h][e] = 0.0f;
#pragma unroll
        for (int h = 0; h < 2; h++) {
#pragma unroll
            for (int c = 0; c < CH; c++) {
                uint4 v = pw[((np * 2 + h) * CH + c) * 32];
#pragma unroll
                for (int m = 0; m < MT; m++) {
                    mma16816(acc[m][h], A[m][2 * c],     v.x, v.y);
                    mma16816(acc[m][h], A[m][2 * c + 1], v.z, v.w);
                }
            }
        }
#pragma unroll
        for (int m = 0; m < MT; m++) {
            O[m][np][0] = cvt_relu2(acc[m][0][0], acc[m][0][1]);
            O[m][np][1] = cvt_relu2(acc[m][0][2], acc[m][0][3]);
            O[m][np][2] = cvt_relu2(acc[m][1][0], acc[m][1][1]);
            O[m][np][3] = cvt_relu2(acc[m][1][2], acc[m][1][3]);
        }
    }
}

}  // namespace

__global__ void __launch_bounds__(THREADS, 5)
nerf_fused_kernel(const float* __restrict__ hash, const float* __restrict__ sh,
                  const float* __restrict__ d0, const float* __restrict__ d1,
                  const float* __restrict__ c0, const float* __restrict__ c1,
                  const float* __restrict__ c2, const float* __restrict__ c3,
                  float* __restrict__ out, int n_tiles) {
    __shared__ SmemLayout S;
    const int tid  = threadIdx.x;
    const int warp = tid >> 5;
    const int lane = tid & 31;
    const int g    = lane >> 2;   // row-in-tile-half
    const int q    = lane & 3;    // column group

    // ---- Stage permuted weights once per CTA ----
    stage_perm(S.p_d0, d0, 64, 32, 8, 1, 0b0101, tid);  // hash: both k-tiles gmem-perm
    stage_perm(S.p_c0, c0, 64, 31, 8, 1, 0b1001, tid);  // kt0: sh gmem-perm, kt1: density shift
    stage_perm(S.p_d1, d1, 16, 64, 2, 2, 0, tid);
    stage_perm(S.p_c1, c1, 64, 64, 8, 2, 0, tid);
    stage_perm(S.p_c2, c2, 64, 64, 8, 2, 0, tid);
    stage_perm(S.p_c3, c3,  3, 64, 1, 2, 0, tid);
    __syncthreads();  // only block barrier

    const uint4* pw_d0 = S.p_d0 + lane;
    const uint4* pw_c0 = S.p_c0 + lane;
    const uint4* pw_d1 = S.p_d1 + lane;
    const uint4* pw_c1 = S.p_c1 + lane;
    const uint4* pw_c2 = S.p_c2 + lane;
    const uint4* pw_c3 = S.p_c3 + lane;
    float4* out4 = reinterpret_cast<float4*>(out);
    const float4* hash4 = reinterpret_cast<const float4*>(hash);  // row = 8 f4
    const float4* sh4   = reinterpret_cast<const float4*>(sh);    // row = 4 f4
    const unsigned FULL = 0xffffffffu;

    for (int tile = blockIdx.x; tile < n_tiles; tile += gridDim.x) {
        const size_t row0 = (size_t)tile * CTA_M + warp * WARP_M;

        uint32_t Aa[MT][4][4];  // ping
        uint32_t Ab[MT][4][4];  // pong; Ab[m][0..1] doubles as 32-wide input

        // ---- hash A frags: one LDG.128 per row-half per k-tile (K-perm) ----
#pragma unroll
        for (int m = 0; m < MT; m++) {
#pragma unroll
            for (int kt = 0; kt < 2; kt++) {
                float4 v0 = __ldcs(hash4 + (row0 + m * 16 + g) * 8 + kt * 4 + q);
                float4 v1 = __ldcs(hash4 + (row0 + m * 16 + g + 8) * 8 + kt * 4 + q);
                Ab[m][kt][0] = h2u(v0.x, v0.y);
                Ab[m][kt][1] = h2u(v1.x, v1.y);
                Ab[m][kt][2] = h2u(v0.z, v0.w);
                Ab[m][kt][3] = h2u(v1.z, v1.w);
            }
        }

        // ---- d0: relu(hash @ d0^T) ----
        layer_chain<2, 4>(Ab, pw_d0, Aa);

        // ---- sh loads issued NOW (into dead Ab[m][0]); d1 hides the latency
#pragma unroll
        for (int m = 0; m < MT; m++) {
            float4 v0 = __ldcs(sh4 + (row0 + m * 16 + g) * 4 + q);
            float4 v1 = __ldcs(sh4 + (row0 + m * 16 + g + 8) * 4 + q);
            Ab[m][0][0] = h2u(v0.x, v0.y);
            Ab[m][0][1] = h2u(v1.x, v1.y);
            Ab[m][0][2] = h2u(v0.z, v0.w);
            Ab[m][0][3] = h2u(v1.z, v1.w);
        }

        // ---- d1: h @ d1^T -> sigma (regs) + raw 16-col output as c0's
        //      k-tile-1 A (identity mapping; the concat shift lives in w_c0)
        float sig[MT][2];
#pragma unroll
        for (int m = 0; m < MT; m++) {
            float dacc[2][4];
#pragma unroll
            for (int h = 0; h < 2; h++)
#pragma unroll
                for (int e = 0; e < 4; e++) dacc[h][e] = 0.0f;
#pragma unroll
            for (int h = 0; h < 2; h++) {
#pragma unroll
                for (int c = 0; c < 2; c++) {
                    uint4 v = pw_d1[(h * 2 + c) * 32];
                    mma16816(dacc[h], Aa[m][2 * c],     v.x, v.y);
                    mma16816(dacc[h], Aa[m][2 * c + 1], v.z, v.w);
                }
            }
            // sigma = D col 0 (meaningful on q==0 = output lanes)
            sig[m][0] = dacc[0][0];
            sig[m][1] = dacc[0][2];
            // identity acc -> A-fragment (no relu on density)
            Ab[m][1][0] = h2u(dacc[0][0], dacc[0][1]);
            Ab[m][1][1] = h2u(dacc[0][2], dacc[0][3]);
            Ab[m][1][2] = h2u(dacc[1][0], dacc[1][1]);
            Ab[m][1][3] = h2u(dacc[1][2], dacc[1][3]);
        }

        // ---- c0, c1, c2 ----
        layer_chain<2, 4>(Ab, pw_c0, Aa);
        layer_chain<4, 4>(Aa, pw_c1, Ab);
        layer_chain<4, 4>(Ab, pw_c2, Aa);

        // ---- c3: color (cols 0..2 of one 8-wide n-tile) ----
        {
            float cacc[MT][4];
#pragma unroll
            for (int m = 0; m < MT; m++)
#pragma unroll
                for (int e = 0; e < 4; e++) cacc[m][e] = 0.0f;
#pragma unroll
            for (int c = 0; c < 2; c++) {
                uint4 v = pw_c3[c * 32];
#pragma unroll
                for (int m = 0; m < MT; m++) {
                    mma16816(cacc[m], Aa[m][2 * c],     v.x, v.y);
                    mma16816(cacc[m], Aa[m][2 * c + 1], v.z, v.w);
                }
            }
#pragma unroll
            for (int m = 0; m < MT; m++) {
                // lane 4g holds cols {0,1}; lane 4g+1 holds col 2
                float b0c = __shfl_down_sync(FULL, cacc[m][0], 1);
                float b1c = __shfl_down_sync(FULL, cacc[m][2], 1);
                if (q == 0) {
                    out4[row0 + m * 16 + g] =
                        make_float4(cacc[m][0], cacc[m][1], b0c, sig[m][0]);
                    out4[row0 + m * 16 + g + 8] =
                        make_float4(cacc[m][2], cacc[m][3], b1c, sig[m][1]);
                }
            }
        }
    }
}

extern "C" void kernel_launch(void* const* d_in, const int* in_sizes, int n_in,
                              void* d_out, int out_size) {
    const float* hash = (const float*)d_in[0];  // [N, 32]
    const float* sh   = (const float*)d_in[1];  // [N, 16]
    const float* d0   = (const float*)d_in[2];  // [64, 32]
    const float* d1   = (const float*)d_in[3];  // [16, 64]
    const float* c0   = (const float*)d_in[4];  // [64, 31]
    const float* c1   = (const float*)d_in[5];  // [64, 64]
    const float* c2   = (const float*)d_in[6];  // [64, 64]
    const float* c3   = (const float*)d_in[7];  // [3, 64]
    float* out = (float*)d_out;                 // [N, 4]

    const int n       = in_sizes[0] / 32;
    const int n_tiles = n / CTA_M;  // 16384

    int grid = 148 * 5;  // persistent, 5 CTAs/SM, 20 warps/SM
    if (grid > n_tiles) grid = n_tiles;

    nerf_fused_kernel<<<grid, THREADS>>>(hash, sh, d0, d1, c0, c1, c2, c3, out,
                                         n_tiles);
}

// round 14
// speedup vs baseline: 1.1708x; 1.0089x over previous
#include <cuda_runtime.h>
#include <cuda_fp16.h>
#include <cstdint>

namespace {

constexpr int THREADS = 128;             // 4 warps/CTA, 6 CTAs/SM -> 24 warps
constexpr int MT      = 2;               // 16-row m-tiles per warp
constexpr int WARP_M  = 16 * MT;         // 32 rows / warp
constexpr int NWARP   = 4;
constexpr int CTA_M   = NWARP * WARP_M;  // 128 rows / CTA

// One flat per-lane permuted weight table; per-layer sections addressed by
// compile-time uint4 offsets (fold into LDS immediate -> one base register).
constexpr int OFF_D0 = 0;            // 8*1*32 = 256
constexpr int OFF_C0 = 256;          // 256
constexpr int OFF_D1 = 512;          // 2*2*32 = 128
constexpr int OFF_C1 = 640;          // 8*2*32 = 512
constexpr int OFF_C2 = 1152;         // 512
constexpr int OFF_C3 = 1664;         // 64
constexpr int TAB_SZ = 1728;         // 27648 B -> 6 CTAs = 166 KB < 228 KB

__device__ __forceinline__ uint32_t h2u(float x, float y) {
    __half2 h = __floats2half2_rn(x, y);
    return *reinterpret_cast<uint32_t*>(&h);
}
// Fused relu + pack: lo = relu(rn(x)), hi = relu(rn(y)). One SASS op.
__device__ __forceinline__ uint32_t cvt_relu2(float x, float y) {
    uint32_t r;
    asm("cvt.rn.relu.f16x2.f32 %0, %1, %2;\n" : "=r"(r) : "f"(y), "f"(x));
    return r;
}

__device__ __forceinline__ void mma16816(float c[4], const uint32_t a[4],
                                         uint32_t b0, uint32_t b1) {
    asm volatile(
        "mma.sync.aligned.m16n8k16.row.col.f32.f16.f16.f32 "
        "{%0,%1,%2,%3},{%4,%5,%6,%7},{%8,%9},{%0,%1,%2,%3};\n"
        : "+f"(c[0]), "+f"(c[1]), "+f"(c[2]), "+f"(c[3])
        : "r"(a[0]), "r"(a[1]), "r"(a[2]), "r"(a[3]), "r"(b0), "r"(b1));
}

// Stage a [Nout x Kin] f32 row-major weight matrix into the permuted table.
// Per-k-tile mode (2 bits each in `modes`):
//   0 = identity        (mma-col t -> W col base + t)
//   1 = gmem K-perm     (cols (2q,2q+1)->(4q,4q+1), (2q+8,+9)->(4q+2,+3))
//   2 = density shift   (mma-col t -> W col 15+t; col 0 -> 0)  [c0 k-tile 1]
__device__ void stage_perm(uint4* dst, const float* __restrict__ W, int Nout,
                           int Kin, int NPH, int CH, int modes, int tid) {
    const int total = NPH * CH * 32;
    for (int e = tid; e < total; e += THREADS) {
        int lane = e & 31;
        int c    = (e >> 5) % CH;
        int nph  = e / (32 * CH);
        int row  = (nph >> 1) * 16 + (nph & 1) * 8 + (lane >> 2);
        int q    = lane & 3;
        auto rd = [&](int cc) -> float {
            return (cc >= 0 && row < Nout && cc < Kin) ? W[row * Kin + cc] : 0.0f;
        };
        auto pack = [&](int kt, int half) -> uint32_t {
            int mode = (modes >> (2 * kt)) & 3;
            int base = kt * 16;
            int t    = 2 * q + (half ? 8 : 0);  // identity mma column
            int ca, cb;
            if (mode == 1) {
                ca = base + 4 * q + (half ? 2 : 0);
                cb = ca + 1;
            } else if (mode == 2) {
                ca = (t == 0) ? -1 : 15 + t;  // col 0 (sigma) contributes 0
                cb = 15 + t + 1;
            } else {
                ca = base + t;
                cb = ca + 1;
            }
            return h2u(rd(ca), rd(cb));
        };
        uint4 v;
        v.x = pack(2 * c,     0);
        v.y = pack(2 * c,     1);
        v.z = pack(2 * c + 1, 0);
        v.w = pack(2 * c + 1, 1);
        dst[e] = v;
    }
}

// Register-chained relu layer: one LDS.128 per (np,h,chunk) feeds 2*MT HMMAs;
// epilogue is one fused cvt.relu per output register.
template <int KT, int NP>
__device__ __forceinline__ void layer_chain(const uint32_t (&A)[MT][4][4],
                                            const uint4* __restrict__ pw,
                                            uint32_t (&O)[MT][4][4]) {
    constexpr int CH = KT / 2;
#pragma unroll
    for (int np = 0; np < NP; np++) {
        float acc[MT][2][4];
#pragma unroll
        for (int m = 0; m < MT; m++)
#pragma unroll
            for (int h = 0; h < 2; h++)
#pragma unroll
                for (int e = 0; e < 4; e++) acc[m][h][e] = 0.0f;
#pragma unroll
        for (int h = 0; h < 2; h++) {
#pragma unroll
            for (int c = 0; c < CH; c++) {
                uint4 v = pw[((np * 2 + h) * CH + c) * 32];
#pragma unroll
                for (int m = 0; m < MT; m++) {
                    mma16816(acc[m][h], A[m][2 * c],     v.x, v.y);
                    mma16816(acc[m][h], A[m][2 * c + 1], v.z, v.w);
                }
            }
        }
#pragma unroll
        for (int m = 0; m < MT; m++) {
            O[m][np][0] = cvt_relu2(acc[m][0][0], acc[m][0][1]);
            O[m][np][1] = cvt_relu2(acc[m][0][2], acc[m][0][3]);
            O[m][np][2] = cvt_relu2(acc[m][1][0], acc[m][1][1]);
            O[m][np][3] = cvt_relu2(acc[m][1][2], acc[m][1][3]);
        }
    }
}

}  // namespace

__global__ void __launch_bounds__(THREADS, 6)
nerf_fused_kernel(const float* __restrict__ hash, const float* __restrict__ sh,
                  const float* __restrict__ d0, const float* __restrict__ d1,
                  const float* __restrict__ c0, const float* __restrict__ c1,
                  const float* __restrict__ c2, const float* __restrict__ c3,
                  float* __restrict__ out, int n_tiles) {
    __shared__ uint4 tab[TAB_SZ];
    const int tid  = threadIdx.x;
    const int warp = tid >> 5;
    const int lane = tid & 31;
    const int g    = lane >> 2;   // row-in-tile-half
    const int q    = lane & 3;    // column group

    // ---- Stage permuted weights once per CTA ----
    stage_perm(tab + OFF_D0, d0, 64, 32, 8, 1, 0b0101, tid);  // hash gmem-perm
    stage_perm(tab + OFF_C0, c0, 64, 31, 8, 1, 0b1001, tid);  // sh perm + density shift
    stage_perm(tab + OFF_D1, d1, 16, 64, 2, 2, 0, tid);
    stage_perm(tab + OFF_C1, c1, 64, 64, 8, 2, 0, tid);
    stage_perm(tab + OFF_C2, c2, 64, 64, 8, 2, 0, tid);
    stage_perm(tab + OFF_C3, c3,  3, 64, 1, 2, 0, tid);
    __syncthreads();  // only block barrier

    const uint4* pwl = tab + lane;  // single per-lane base; sections by imm
    const float4* hash4 = reinterpret_cast<const float4*>(hash);  // row = 8 f4
    const float4* sh4   = reinterpret_cast<const float4*>(sh);    // row = 4 f4
    const unsigned FULL = 0xffffffffu;

    for (int tile = blockIdx.x; tile < n_tiles; tile += gridDim.x) {
        const int row0 = tile * CTA_M + warp * WARP_M;

        uint32_t Aa[MT][4][4];  // ping
        uint32_t Ab[MT][4][4];  // pong; Ab[m][0..1] doubles as 32-wide input

        // ---- hash A frags: one LDG.128 per row-half per k-tile (K-perm) ----
#pragma unroll
        for (int m = 0; m < MT; m++) {
#pragma unroll
            for (int kt = 0; kt < 2; kt++) {
                float4 v0 = __ldcs(hash4 + (row0 + m * 16 + g) * 8 + kt * 4 + q);
                float4 v1 = __ldcs(hash4 + (row0 + m * 16 + g + 8) * 8 + kt * 4 + q);
                Ab[m][kt][0] = h2u(v0.x, v0.y);
                Ab[m][kt][1] = h2u(v1.x, v1.y);
                Ab[m][kt][2] = h2u(v0.z, v0.w);
                Ab[m][kt][3] = h2u(v1.z, v1.w);
            }
        }

        // ---- d0: relu(hash @ d0^T) ----
        layer_chain<2, 4>(Ab, pwl + OFF_D0, Aa);

        // ---- sh loads issued NOW (into dead Ab[m][0]); d1 hides the latency
#pragma unroll
        for (int m = 0; m < MT; m++) {
            float4 v0 = __ldcs(sh4 + (row0 + m * 16 + g) * 4 + q);
            float4 v1 = __ldcs(sh4 + (row0 + m * 16 + g + 8) * 4 + q);
            Ab[m][0][0] = h2u(v0.x, v0.y);
            Ab[m][0][1] = h2u(v1.x, v1.y);
            Ab[m][0][2] = h2u(v0.z, v0.w);
            Ab[m][0][3] = h2u(v1.z, v1.w);
        }

        // ---- d1: h @ d1^T -> sigma straight to gmem (register diet);
        //      raw 16-col output is c0's k-tile-1 A (shift lives in w_c0)
#pragma unroll
        for (int m = 0; m < MT; m++) {
            float dacc[2][4];
#pragma unroll
            for (int h = 0; h < 2; h++)
#pragma unroll
                for (int e = 0; e < 4; e++) dacc[h][e] = 0.0f;
#pragma unroll
            for (int h = 0; h < 2; h++) {
#pragma unroll
                for (int c = 0; c < 2; c++) {
                    uint4 v = pwl[OFF_D1 + (h * 2 + c) * 32];
                    mma16816(dacc[h], Aa[m][2 * c],     v.x, v.y);
                    mma16816(dacc[h], Aa[m][2 * c + 1], v.z, v.w);
                }
            }
            if (q == 0) {  // sigma = D col 0, written immediately
                out[(row0 + m * 16 + g) * 4 + 3]     = dacc[0][0];
                out[(row0 + m * 16 + g + 8) * 4 + 3] = dacc[0][2];
            }
            // identity acc -> A-fragment (no relu on density)
            Ab[m][1][0] = h2u(dacc[0][0], dacc[0][1]);
            Ab[m][1][1] = h2u(dacc[0][2], dacc[0][3]);
            Ab[m][1][2] = h2u(dacc[1][0], dacc[1][1]);
            Ab[m][1][3] = h2u(dacc[1][2], dacc[1][3]);
        }

        // ---- c0, c1, c2 ----
        layer_chain<2, 4>(Ab, pwl + OFF_C0, Aa);
        layer_chain<4, 4>(Aa, pwl + OFF_C1, Ab);
        layer_chain<4, 4>(Ab, pwl + OFF_C2, Aa);

        // ---- c3: color (cols 0..2 of one 8-wide n-tile) ----
        {
            float cacc[MT][4];
#pragma unroll
            for (int m = 0; m < MT; m++)
#pragma unroll
                for (int e = 0; e < 4; e++) cacc[m][e] = 0.0f;
#pragma unroll
            for (int c = 0; c < 2; c++) {
                uint4 v = pwl[OFF_C3 + c * 32];
#pragma unroll
                for (int m = 0; m < MT; m++) {
                    mma16816(cacc[m], Aa[m][2 * c],     v.x, v.y);
                    mma16816(cacc[m], Aa[m][2 * c + 1], v.z, v.w);
                }
            }
#pragma unroll
            for (int m = 0; m < MT; m++) {
                // lane 4g holds cols {0,1}; lane 4g+1 holds col 2
                float b0c = __shfl_down_sync(FULL, cacc[m][0], 1);
                float b1c = __shfl_down_sync(FULL, cacc[m][2], 1);
                if (q == 0) {  // color only; sigma already written
                    int r0 = (row0 + m * 16 + g) * 4;
                    int r1 = (row0 + m * 16 + g + 8) * 4;
                    *reinterpret_cast<float2*>(out + r0) =
                        make_float2(cacc[m][0], cacc[m][1]);
                    out[r0 + 2] = b0c;
                    *reinterpret_cast<float2*>(out + r1) =
                        make_float2(cacc[m][2], cacc[m][3]);
                    out[r1 + 2] = b1c;
                }
            }
        }
    }
}

extern "C" void kernel_launch(void* const* d_in, const int* in_sizes, int n_in,
                              void* d_out, int out_size) {
    const float* hash = (const float*)d_in[0];  // [N, 32]
    const float* sh   = (const float*)d_in[1];  // [N, 16]
    const float* d0   = (const float*)d_in[2];  // [64, 32]
    const float* d1   = (const float*)d_in[3];  // [16, 64]
    const float* c0   = (const float*)d_in[4];  // [64, 31]
    const float* c1   = (const float*)d_in[5];  // [64, 64]
    const float* c2   = (const float*)d_in[6];  // [64, 64]
    const float* c3   = (const float*)d_in[7];  // [3, 64]
    float* out = (float*)d_out;                 // [N, 4]

    const int n       = in_sizes[0] / 32;
    const int n_tiles = n / CTA_M;  // 16384

    int grid = 148 * 6;  // persistent, 6 CTAs/SM, 24 warps/SM
    if (grid > n_tiles) grid = n_tiles;

    nerf_fused_kernel<<<grid, THREADS>>>(hash, sh, d0, d1, c0, c1, c2, c3, out,
                                         n_tiles);
}